// round 12
// baseline (speedup 1.0000x reference)
#include <cuda_runtime.h>
#include <math.h>

#define C_CLASSES 32000
#define NROWS     8192
#define THREADS   256

// float32(log(32000.0))
#define TAU_F 10.373491181781864f
// float32(-2.0/math.e)
#define NEG2_OVER_E -0.7357588823428847f

__device__ float    g_sum = 0.0f;
__device__ unsigned g_done_ctr = 0;

// fp32 Lambert W0, reference's 12 Halley iterations
__device__ __forceinline__ float lambertw0_f(float y) {
    const float E = 2.7182818284590452f;
    float w;
    if (y < 0.0f) {
        w = -1.0f + sqrtf(fmaxf(2.0f * (E * y + 1.0f), 0.0f));
    } else {
        w = log1pf(y);
    }
#pragma unroll
    for (int it = 0; it < 12; ++it) {
        float ew   = expf(w);
        float f    = w * ew - y;
        float wp1  = w + 1.0f;
        float swp1 = (fabsf(wp1) < 1e-6f) ? 1e-6f : wp1;
        float den  = ew * wp1 - (w + 2.0f) * f / (2.0f * swp1);
        float sden = (fabsf(den) < 1e-30f) ? 1e-30f : den;
        w = w - f / sden;
    }
    return w;
}

__global__ void __launch_bounds__(THREADS)
superloss_kernel(const float* __restrict__ logits,
                 const int*   __restrict__ targets,
                 const float* __restrict__ class_weights,
                 float*       __restrict__ out) {
    const int row = blockIdx.x;
    const int tid = threadIdx.x;

    const float4* rowp = reinterpret_cast<const float4*>(logits + (size_t)row * C_CLASSES);
    const int nvec = C_CLASSES / 4;  // 8000

    // FROZEN arithmetic order (R5/R7/R8): same index sequence, same single
    // accumulator, same __expf per element. Only change vs R8: unroll 8 -> 16
    // (pure load batching; does not reassociate the FADD chain).
    float s = 0.0f;
#pragma unroll 16
    for (int i = tid; i < nvec; i += THREADS) {
        float4 v = __ldcs(&rowp[i]);
        s += __expf(v.x);
        s += __expf(v.y);
        s += __expf(v.z);
        s += __expf(v.w);
    }

#pragma unroll
    for (int o = 16; o > 0; o >>= 1)
        s += __shfl_xor_sync(0xffffffffu, s, o);

    __shared__ float warp_sums[THREADS / 32];
    const int wid = tid >> 5;
    const int lid = tid & 31;
    if (lid == 0) warp_sums[wid] = s;
    __syncthreads();

    if (tid == 0) {
        float tot = 0.0f;
#pragma unroll
        for (int i = 0; i < THREADS / 32; ++i) tot += warp_sums[i];

        const int   t   = targets[row];
        const float xt  = __ldg(&logits[(size_t)row * C_CLASSES + t]);
        const float lse = logf(tot);
        const float wt  = __ldg(&class_weights[t]);
        const float l   = (lse - xt) * wt;   // weighted NLL

        float y = 0.5f * fmaxf(NEG2_OVER_E, l - TAU_F);
        y = fminf(fmaxf(y, -1.0f), 10.0f);
        const float w     = lambertw0_f(y);
        const float sigma = expf(-w);

        const float loss = (l - TAU_F) * sigma;

        atomicAdd(&g_sum, loss);
        __threadfence();
        unsigned prev = atomicAdd(&g_done_ctr, 1u);
        if (prev == NROWS - 1u) {
            __threadfence();
            out[0] = g_sum / (float)NROWS;
            g_sum = 0.0f;        // reset for next graph replay
            g_done_ctr = 0;
        }
    }
}

extern "C" void kernel_launch(void* const* d_in, const int* in_sizes, int n_in,
                              void* d_out, int out_size) {
    const float* logits        = (const float*)d_in[0];
    const int*   targets       = (const int*)d_in[1];
    const float* class_weights = (const float*)d_in[2];
    float* out = (float*)d_out;

    superloss_kernel<<<NROWS, THREADS>>>(logits, targets, class_weights, out);
}

// round 13
// speedup vs baseline: 1.0200x; 1.0200x over previous
#include <cuda_runtime.h>
#include <math.h>

#define C_CLASSES 32000
#define NROWS     8192
#define THREADS   256

// float32(log(32000.0))
#define TAU_F 10.373491181781864f
// float32(-2.0/math.e)
#define NEG2_OVER_E -0.7357588823428847f

__device__ float    g_sum = 0.0f;
__device__ unsigned g_done_ctr = 0;

// fp32 Lambert W0, reference's 12 Halley iterations
__device__ __forceinline__ float lambertw0_f(float y) {
    const float E = 2.7182818284590452f;
    float w;
    if (y < 0.0f) {
        w = -1.0f + sqrtf(fmaxf(2.0f * (E * y + 1.0f), 0.0f));
    } else {
        w = log1pf(y);
    }
#pragma unroll
    for (int it = 0; it < 12; ++it) {
        float ew   = expf(w);
        float f    = w * ew - y;
        float wp1  = w + 1.0f;
        float swp1 = (fabsf(wp1) < 1e-6f) ? 1e-6f : wp1;
        float den  = ew * wp1 - (w + 2.0f) * f / (2.0f * swp1);
        float sden = (fabsf(den) < 1e-30f) ? 1e-30f : den;
        w = w - f / sden;
    }
    return w;
}

__global__ void __launch_bounds__(THREADS)
superloss_kernel(const float* __restrict__ logits,
                 const int*   __restrict__ targets,
                 const float* __restrict__ class_weights,
                 float*       __restrict__ out) {
    const int row = blockIdx.x;
    const int tid = threadIdx.x;

    const float4* rowp = reinterpret_cast<const float4*>(logits + (size_t)row * C_CLASSES);
    const int nvec = C_CLASSES / 4;  // 8000

    // FROZEN arithmetic order (R5/R7/R8): block-per-row, float4, single
    // accumulator, __expf per element, __ldcs streaming. unroll 8 is the
    // measured optimum (4: 151.6us, 8: 150.4us, 16: 155.4us).
    float s = 0.0f;
#pragma unroll 8
    for (int i = tid; i < nvec; i += THREADS) {
        float4 v = __ldcs(&rowp[i]);
        s += __expf(v.x);
        s += __expf(v.y);
        s += __expf(v.z);
        s += __expf(v.w);
    }

#pragma unroll
    for (int o = 16; o > 0; o >>= 1)
        s += __shfl_xor_sync(0xffffffffu, s, o);

    __shared__ float warp_sums[THREADS / 32];
    const int wid = tid >> 5;
    const int lid = tid & 31;
    if (lid == 0) warp_sums[wid] = s;
    __syncthreads();

    if (tid == 0) {
        float tot = 0.0f;
#pragma unroll
        for (int i = 0; i < THREADS / 32; ++i) tot += warp_sums[i];

        const int   t   = targets[row];
        const float xt  = __ldg(&logits[(size_t)row * C_CLASSES + t]);
        const float lse = logf(tot);
        const float wt  = __ldg(&class_weights[t]);
        const float l   = (lse - xt) * wt;   // weighted NLL

        float y = 0.5f * fmaxf(NEG2_OVER_E, l - TAU_F);
        y = fminf(fmaxf(y, -1.0f), 10.0f);
        const float w     = lambertw0_f(y);
        const float sigma = expf(-w);

        const float loss = (l - TAU_F) * sigma;

        atomicAdd(&g_sum, loss);
        __threadfence();
        unsigned prev = atomicAdd(&g_done_ctr, 1u);
        if (prev == NROWS - 1u) {
            __threadfence();
            out[0] = g_sum / (float)NROWS;
            g_sum = 0.0f;        // reset for next graph replay
            g_done_ctr = 0;
        }
    }
}

extern "C" void kernel_launch(void* const* d_in, const int* in_sizes, int n_in,
                              void* d_out, int out_size) {
    const float* logits        = (const float*)d_in[0];
    const int*   targets       = (const int*)d_in[1];
    const float* class_weights = (const float*)d_in[2];
    float* out = (float*)d_out;

    superloss_kernel<<<NROWS, THREADS>>>(logits, targets, class_weights, out);
}

// round 14
// speedup vs baseline: 1.0358x; 1.0156x over previous
#include <cuda_runtime.h>
#include <math.h>

#define C_CLASSES 32000
#define NROWS     8192
#define THREADS   256

// float32(log(32000.0))
#define TAU_F 10.373491181781864f
// float32(-2.0/math.e)
#define NEG2_OVER_E -0.7357588823428847f

__device__ float    g_sum = 0.0f;
__device__ unsigned g_done_ctr = 0;

// fp32 Lambert W0, reference's 12 Halley iterations
__device__ __forceinline__ float lambertw0_f(float y) {
    const float E = 2.7182818284590452f;
    float w;
    if (y < 0.0f) {
        w = -1.0f + sqrtf(fmaxf(2.0f * (E * y + 1.0f), 0.0f));
    } else {
        w = log1pf(y);
    }
#pragma unroll
    for (int it = 0; it < 12; ++it) {
        float ew   = expf(w);
        float f    = w * ew - y;
        float wp1  = w + 1.0f;
        float swp1 = (fabsf(wp1) < 1e-6f) ? 1e-6f : wp1;
        float den  = ew * wp1 - (w + 2.0f) * f / (2.0f * swp1);
        float sden = (fabsf(den) < 1e-30f) ? 1e-30f : den;
        w = w - f / sden;
    }
    return w;
}

__global__ void __launch_bounds__(THREADS)
superloss_kernel(const float* __restrict__ logits,
                 const int*   __restrict__ targets,
                 const float* __restrict__ class_weights,
                 float*       __restrict__ out) {
    const int row = blockIdx.x;
    const int tid = threadIdx.x;

    // Hoisted epilogue gathers (thread 0 only): issue the dependent
    // targets->logits/weights chain BEFORE the streaming loop so its
    // ~2x577cyc DRAM latency hides under the 250-iteration stream.
    // Loop-invariant, same addresses/values -> bit-identical result.
    int   t  = 0;
    float xt = 0.0f, wt = 0.0f;
    if (tid == 0) {
        t  = targets[row];
        xt = __ldg(&logits[(size_t)row * C_CLASSES + t]);
        wt = __ldg(&class_weights[t]);
    }

    const float4* rowp = reinterpret_cast<const float4*>(logits + (size_t)row * C_CLASSES);
    const int nvec = C_CLASSES / 4;  // 8000

    // FROZEN arithmetic order (R5/R7/R8): block-per-row, float4, single
    // accumulator, __expf per element, __ldcs streaming, unroll 8 (measured
    // optimum: 4 -> 151.6us, 8 -> 150.4us, 16 -> 155.4us).
    float s = 0.0f;
#pragma unroll 8
    for (int i = tid; i < nvec; i += THREADS) {
        float4 v = __ldcs(&rowp[i]);
        s += __expf(v.x);
        s += __expf(v.y);
        s += __expf(v.z);
        s += __expf(v.w);
    }

#pragma unroll
    for (int o = 16; o > 0; o >>= 1)
        s += __shfl_xor_sync(0xffffffffu, s, o);

    __shared__ float warp_sums[THREADS / 32];
    const int wid = tid >> 5;
    const int lid = tid & 31;
    if (lid == 0) warp_sums[wid] = s;
    __syncthreads();

    if (tid == 0) {
        float tot = 0.0f;
#pragma unroll
        for (int i = 0; i < THREADS / 32; ++i) tot += warp_sums[i];

        const float lse = logf(tot);
        const float l   = (lse - xt) * wt;   // weighted NLL

        float y = 0.5f * fmaxf(NEG2_OVER_E, l - TAU_F);
        y = fminf(fmaxf(y, -1.0f), 10.0f);
        const float w     = lambertw0_f(y);
        const float sigma = expf(-w);

        const float loss = (l - TAU_F) * sigma;

        atomicAdd(&g_sum, loss);
        __threadfence();
        unsigned prev = atomicAdd(&g_done_ctr, 1u);
        if (prev == NROWS - 1u) {
            __threadfence();
            out[0] = g_sum / (float)NROWS;
            g_sum = 0.0f;        // reset for next graph replay
            g_done_ctr = 0;
        }
    }
}

extern "C" void kernel_launch(void* const* d_in, const int* in_sizes, int n_in,
                              void* d_out, int out_size) {
    const float* logits        = (const float*)d_in[0];
    const int*   targets       = (const int*)d_in[1];
    const float* class_weights = (const float*)d_in[2];
    float* out = (float*)d_out;

    superloss_kernel<<<NROWS, THREADS>>>(logits, targets, class_weights, out);
}